// round 1
// baseline (speedup 1.0000x reference)
#include <cuda_runtime.h>
#include <math.h>

#define L   4096
#define H   1024
#define FF  512
#define NE  8
#define NTOPK 2
#define ROWS (L * NTOPK)

#define BM 128
#define BN 128
#define BK 16

// ---------------- static scratch (no runtime allocation allowed) ----------------
__device__ int   g_count[NE];
__device__ int   g_off[NE];
__device__ int   g_fill[NE];
__device__ int   g_top[L * NTOPK];
__device__ float g_tprob[L * NTOPK];
__device__ int   g_perm[ROWS];
__device__ float g_prob[ROWS];
__device__ float g_h[(size_t)ROWS * (2 * FF)];   // GEMM1 output (gate|up)
__device__ float g_act[(size_t)ROWS * FF];       // silu(g)*u

// ---------------- init ----------------
__global__ void zero_kernel(float* out) {
    int i = blockIdx.x * blockDim.x + threadIdx.x;
    if (i < L * H) out[i] = 0.f;
    if (i < NE) { g_count[i] = 0; g_fill[i] = 0; }
}

// ---------------- router: one warp per token ----------------
__global__ void router_kernel(const float* __restrict__ x, const float* __restrict__ gw) {
    int gid  = blockIdx.x * blockDim.x + threadIdx.x;
    int tok  = gid >> 5;
    int lane = gid & 31;
    if (tok >= L) return;
    const float* xr = x + (size_t)tok * H;
    float acc[NE];
#pragma unroll
    for (int e = 0; e < NE; e++) acc[e] = 0.f;
    for (int h = lane; h < H; h += 32) {
        float xv = xr[h];
#pragma unroll
        for (int e = 0; e < NE; e++) acc[e] = fmaf(xv, gw[e * H + h], acc[e]);
    }
#pragma unroll
    for (int e = 0; e < NE; e++) {
#pragma unroll
        for (int o = 16; o > 0; o >>= 1) acc[e] += __shfl_xor_sync(0xffffffffu, acc[e], o);
    }
    if (lane == 0) {
        // top-2 on logits (softmax is monotone); first-occurrence tie-break like jax top_k
        int i0 = 0;
#pragma unroll
        for (int e = 1; e < NE; e++) if (acc[e] > acc[i0]) i0 = e;
        int i1 = (i0 == 0) ? 1 : 0;
#pragma unroll
        for (int e = 0; e < NE; e++) if (e != i0 && acc[e] > acc[i1]) i1 = e;
        float m  = fmaxf(acc[i0], acc[i1]);
        float e0 = expf(acc[i0] - m), e1 = expf(acc[i1] - m);
        float inv = 1.f / (e0 + e1);
        g_top[tok * 2]     = i0;
        g_top[tok * 2 + 1] = i1;
        g_tprob[tok * 2]     = e0 * inv;
        g_tprob[tok * 2 + 1] = e1 * inv;
        atomicAdd(&g_count[i0], 1);
        atomicAdd(&g_count[i1], 1);
    }
}

__global__ void prefix_kernel() {
    if (threadIdx.x == 0) {
        int s = 0;
        for (int e = 0; e < NE; e++) { g_off[e] = s; s += g_count[e]; }
    }
}

__global__ void scatter_kernel() {
    int tok = blockIdx.x * blockDim.x + threadIdx.x;
    if (tok >= L) return;
#pragma unroll
    for (int j = 0; j < NTOPK; j++) {
        int e   = g_top[tok * 2 + j];
        int pos = atomicAdd(&g_fill[e], 1);
        int r   = g_off[e] + pos;
        g_perm[r] = tok;
        g_prob[r] = g_tprob[tok * 2 + j];
    }
}

// ---------------- GEMM1: h[r, 0:2F] = x[perm[r], :] @ w13[e].T ----------------
__global__ void __launch_bounds__(256) gemm1_kernel(const float* __restrict__ x,
                                                    const float* __restrict__ w13) {
    int e   = blockIdx.z;
    int cnt = g_count[e];
    int m0  = blockIdx.y * BM;
    if (m0 >= cnt) return;
    int n0  = blockIdx.x * BN;
    int off = g_off[e];
    const float* B = w13 + (size_t)e * (2 * FF) * H;

    __shared__ float As[BK][BM];
    __shared__ float Bs[BK][BN];

    int tid = threadIdx.x;
    int tx = tid % 16, ty = tid / 16;

    // loader mapping: tile = 128 rows x 16 k = 512 float4; thread does v=tid, v=tid+256
    int rowA0 = tid >> 2;          // 0..63
    int rowA1 = (tid + 256) >> 2;  // 64..127
    int kq    = tid & 3;

    int tokA0 = (m0 + rowA0 < cnt) ? g_perm[off + m0 + rowA0] : -1;
    int tokA1 = (m0 + rowA1 < cnt) ? g_perm[off + m0 + rowA1] : -1;

    float acc[8][8];
#pragma unroll
    for (int i = 0; i < 8; i++)
#pragma unroll
        for (int j = 0; j < 8; j++) acc[i][j] = 0.f;

    const float4 z4 = make_float4(0.f, 0.f, 0.f, 0.f);

    for (int k0 = 0; k0 < H; k0 += BK) {
        float4 a0 = (tokA0 >= 0) ? *(const float4*)&x[(size_t)tokA0 * H + k0 + kq * 4] : z4;
        float4 a1 = (tokA1 >= 0) ? *(const float4*)&x[(size_t)tokA1 * H + k0 + kq * 4] : z4;
        float4 b0 = *(const float4*)&B[(size_t)(n0 + rowA0) * H + k0 + kq * 4];
        float4 b1 = *(const float4*)&B[(size_t)(n0 + rowA1) * H + k0 + kq * 4];
        As[kq * 4 + 0][rowA0] = a0.x; As[kq * 4 + 1][rowA0] = a0.y;
        As[kq * 4 + 2][rowA0] = a0.z; As[kq * 4 + 3][rowA0] = a0.w;
        As[kq * 4 + 0][rowA1] = a1.x; As[kq * 4 + 1][rowA1] = a1.y;
        As[kq * 4 + 2][rowA1] = a1.z; As[kq * 4 + 3][rowA1] = a1.w;
        Bs[kq * 4 + 0][rowA0] = b0.x; Bs[kq * 4 + 1][rowA0] = b0.y;
        Bs[kq * 4 + 2][rowA0] = b0.z; Bs[kq * 4 + 3][rowA0] = b0.w;
        Bs[kq * 4 + 0][rowA1] = b1.x; Bs[kq * 4 + 1][rowA1] = b1.y;
        Bs[kq * 4 + 2][rowA1] = b1.z; Bs[kq * 4 + 3][rowA1] = b1.w;
        __syncthreads();
#pragma unroll
        for (int kk = 0; kk < BK; kk++) {
            float4 aA = *(float4*)&As[kk][ty * 8];
            float4 aB = *(float4*)&As[kk][ty * 8 + 4];
            float4 bA = *(float4*)&Bs[kk][tx * 8];
            float4 bB = *(float4*)&Bs[kk][tx * 8 + 4];
            float ra[8] = {aA.x, aA.y, aA.z, aA.w, aB.x, aB.y, aB.z, aB.w};
            float rb[8] = {bA.x, bA.y, bA.z, bA.w, bB.x, bB.y, bB.z, bB.w};
#pragma unroll
            for (int i = 0; i < 8; i++)
#pragma unroll
                for (int j = 0; j < 8; j++) acc[i][j] = fmaf(ra[i], rb[j], acc[i][j]);
        }
        __syncthreads();
    }

#pragma unroll
    for (int i = 0; i < 8; i++) {
        int m = m0 + ty * 8 + i;
        if (m < cnt) {
            float* c = &g_h[(size_t)(off + m) * (2 * FF) + n0 + tx * 8];
            *(float4*)c       = make_float4(acc[i][0], acc[i][1], acc[i][2], acc[i][3]);
            *(float4*)(c + 4) = make_float4(acc[i][4], acc[i][5], acc[i][6], acc[i][7]);
        }
    }
}

// ---------------- activation: act = silu(g) * u ----------------
__global__ void act_kernel() {
    int i = blockIdx.x * blockDim.x + threadIdx.x;
    if (i >= ROWS * FF) return;
    int r = i / FF, f = i % FF;
    float g = g_h[(size_t)r * (2 * FF) + f];
    float u = g_h[(size_t)r * (2 * FF) + FF + f];
    g_act[i] = (g / (1.f + expf(-g))) * u;
}

// ---------------- GEMM2: y = act @ w2[e].T, atomic-combine into out ----------------
__global__ void __launch_bounds__(256) gemm2_kernel(const float* __restrict__ w2,
                                                    float* __restrict__ out) {
    int e   = blockIdx.z;
    int cnt = g_count[e];
    int m0  = blockIdx.y * BM;
    if (m0 >= cnt) return;
    int n0  = blockIdx.x * BN;
    int off = g_off[e];
    const float* B = w2 + (size_t)e * H * FF;

    __shared__ float As[BK][BM];
    __shared__ float Bs[BK][BN];

    int tid = threadIdx.x;
    int tx = tid % 16, ty = tid / 16;
    int rowA0 = tid >> 2;
    int rowA1 = (tid + 256) >> 2;
    int kq    = tid & 3;

    bool v0 = (m0 + rowA0 < cnt);
    bool v1 = (m0 + rowA1 < cnt);

    float acc[8][8];
#pragma unroll
    for (int i = 0; i < 8; i++)
#pragma unroll
        for (int j = 0; j < 8; j++) acc[i][j] = 0.f;

    const float4 z4 = make_float4(0.f, 0.f, 0.f, 0.f);

    for (int k0 = 0; k0 < FF; k0 += BK) {
        float4 a0 = v0 ? *(const float4*)&g_act[(size_t)(off + m0 + rowA0) * FF + k0 + kq * 4] : z4;
        float4 a1 = v1 ? *(const float4*)&g_act[(size_t)(off + m0 + rowA1) * FF + k0 + kq * 4] : z4;
        float4 b0 = *(const float4*)&B[(size_t)(n0 + rowA0) * FF + k0 + kq * 4];
        float4 b1 = *(const float4*)&B[(size_t)(n0 + rowA1) * FF + k0 + kq * 4];
        As[kq * 4 + 0][rowA0] = a0.x; As[kq * 4 + 1][rowA0] = a0.y;
        As[kq * 4 + 2][rowA0] = a0.z; As[kq * 4 + 3][rowA0] = a0.w;
        As[kq * 4 + 0][rowA1] = a1.x; As[kq * 4 + 1][rowA1] = a1.y;
        As[kq * 4 + 2][rowA1] = a1.z; As[kq * 4 + 3][rowA1] = a1.w;
        Bs[kq * 4 + 0][rowA0] = b0.x; Bs[kq * 4 + 1][rowA0] = b0.y;
        Bs[kq * 4 + 2][rowA0] = b0.z; Bs[kq * 4 + 3][rowA0] = b0.w;
        Bs[kq * 4 + 0][rowA1] = b1.x; Bs[kq * 4 + 1][rowA1] = b1.y;
        Bs[kq * 4 + 2][rowA1] = b1.z; Bs[kq * 4 + 3][rowA1] = b1.w;
        __syncthreads();
#pragma unroll
        for (int kk = 0; kk < BK; kk++) {
            float4 aA = *(float4*)&As[kk][ty * 8];
            float4 aB = *(float4*)&As[kk][ty * 8 + 4];
            float4 bA = *(float4*)&Bs[kk][tx * 8];
            float4 bB = *(float4*)&Bs[kk][tx * 8 + 4];
            float ra[8] = {aA.x, aA.y, aA.z, aA.w, aB.x, aB.y, aB.z, aB.w};
            float rb[8] = {bA.x, bA.y, bA.z, bA.w, bB.x, bB.y, bB.z, bB.w};
#pragma unroll
            for (int i = 0; i < 8; i++)
#pragma unroll
                for (int j = 0; j < 8; j++) acc[i][j] = fmaf(ra[i], rb[j], acc[i][j]);
        }
        __syncthreads();
    }

    // combine: out[token, n] += prob * y  (exactly 2 commutative adds per element -> deterministic)
#pragma unroll
    for (int i = 0; i < 8; i++) {
        int m = m0 + ty * 8 + i;
        if (m < cnt) {
            int   r   = off + m;
            int   tok = g_perm[r];
            float p   = g_prob[r];
            float* o  = &out[(size_t)tok * H + n0 + tx * 8];
#pragma unroll
            for (int j = 0; j < 8; j++) atomicAdd(&o[j], p * acc[i][j]);
        }
    }
}

// ---------------- launch ----------------
extern "C" void kernel_launch(void* const* d_in, const int* in_sizes, int n_in,
                              void* d_out, int out_size) {
    const float* x   = (const float*)d_in[0];
    const float* gw  = (const float*)d_in[1];
    const float* w13 = (const float*)d_in[2];
    const float* w2  = (const float*)d_in[3];
    float* out = (float*)d_out;

    zero_kernel<<<(L * H + 255) / 256, 256>>>(out);
    router_kernel<<<(L * 32 + 255) / 256, 256>>>(x, gw);
    prefix_kernel<<<1, 32>>>();
    scatter_kernel<<<(L + 255) / 256, 256>>>();
    gemm1_kernel<<<dim3((2 * FF) / BN, L / BM, NE), 256>>>(x, w13);
    act_kernel<<<(ROWS * FF + 255) / 256, 256>>>();
    gemm2_kernel<<<dim3(H / BN, L / BM, NE), 256>>>(w2, out);
}

// round 2
// speedup vs baseline: 2.2022x; 2.2022x over previous
#include <cuda_runtime.h>
#include <math.h>
#include <stdint.h>

#define L   4096
#define H   1024
#define FF  512
#define NE  8
#define ROWS (L * 2)
#define BK  16

// ---------------- static scratch ----------------
__device__ int   g_count[NE];
__device__ int   g_off[NE];
__device__ int   g_fill[NE];
__device__ int   g_top[L * 2];
__device__ float g_tprob[L * 2];
__device__ int   g_perm[ROWS];
__device__ float g_prob[ROWS];
__device__ float g_act[(size_t)ROWS * FF];

__device__ __forceinline__ uint32_t f2tf(float f) {
    uint32_t u;
    asm("cvt.rna.tf32.f32 %0, %1;" : "=r"(u) : "f"(f));
    return u;
}

__device__ __forceinline__ void mma8(float* c,
                                     uint32_t a0, uint32_t a1, uint32_t a2, uint32_t a3,
                                     uint32_t b0, uint32_t b1) {
    asm volatile(
        "mma.sync.aligned.m16n8k8.row.col.f32.tf32.tf32.f32 "
        "{%0,%1,%2,%3}, {%4,%5,%6,%7}, {%8,%9}, {%0,%1,%2,%3};"
        : "+f"(c[0]), "+f"(c[1]), "+f"(c[2]), "+f"(c[3])
        : "r"(a0), "r"(a1), "r"(a2), "r"(a3), "r"(b0), "r"(b1));
}

// ---------------- init ----------------
__global__ void zero_kernel(float* out) {
    int i = blockIdx.x * blockDim.x + threadIdx.x;
    if (i < L * H) out[i] = 0.f;
    if (i < NE) { g_count[i] = 0; g_fill[i] = 0; }
}

// ---------------- router: one warp per token ----------------
__global__ void router_kernel(const float* __restrict__ x, const float* __restrict__ gw) {
    int gid  = blockIdx.x * blockDim.x + threadIdx.x;
    int tok  = gid >> 5;
    int lane = gid & 31;
    if (tok >= L) return;
    const float* xr = x + (size_t)tok * H;
    float acc[NE];
#pragma unroll
    for (int e = 0; e < NE; e++) acc[e] = 0.f;
    for (int h = lane; h < H; h += 32) {
        float xv = xr[h];
#pragma unroll
        for (int e = 0; e < NE; e++) acc[e] = fmaf(xv, gw[e * H + h], acc[e]);
    }
#pragma unroll
    for (int e = 0; e < NE; e++) {
#pragma unroll
        for (int o = 16; o > 0; o >>= 1) acc[e] += __shfl_xor_sync(0xffffffffu, acc[e], o);
    }
    if (lane == 0) {
        int i0 = 0;
#pragma unroll
        for (int e = 1; e < NE; e++) if (acc[e] > acc[i0]) i0 = e;
        int i1 = (i0 == 0) ? 1 : 0;
#pragma unroll
        for (int e = 0; e < NE; e++) if (e != i0 && acc[e] > acc[i1]) i1 = e;
        float m  = fmaxf(acc[i0], acc[i1]);
        float e0 = expf(acc[i0] - m), e1 = expf(acc[i1] - m);
        float inv = 1.f / (e0 + e1);
        g_top[tok * 2]     = i0;
        g_top[tok * 2 + 1] = i1;
        g_tprob[tok * 2]     = e0 * inv;
        g_tprob[tok * 2 + 1] = e1 * inv;
        atomicAdd(&g_count[i0], 1);
        atomicAdd(&g_count[i1], 1);
    }
}

__global__ void prefix_kernel() {
    if (threadIdx.x == 0) {
        int s = 0;
        for (int e = 0; e < NE; e++) { g_off[e] = s; s += g_count[e]; }
    }
}

__global__ void scatter_kernel() {
    int tok = blockIdx.x * blockDim.x + threadIdx.x;
    if (tok >= L) return;
#pragma unroll
    for (int j = 0; j < 2; j++) {
        int e   = g_top[tok * 2 + j];
        int pos = atomicAdd(&g_fill[e], 1);
        int r   = g_off[e] + pos;
        g_perm[r] = tok;
        g_prob[r] = g_tprob[tok * 2 + j];
    }
}

// ================= GEMM1 fused with SwiGLU =================
// act[r, n] = silu(x[perm[r]] . w13[e][n]) * (x[perm[r]] . w13[e][512+n])
// Block: 256 thr, tile M=128 x N=64 (gate + up pair). Warps 4(m) x 2(n); warp tile 32x32 per matrix.
__global__ void __launch_bounds__(256) gemm1_kernel(const float* __restrict__ x,
                                                    const float* __restrict__ w13) {
    int e   = blockIdx.z;
    int cnt = g_count[e];
    int m0  = blockIdx.y * 128;
    if (m0 >= cnt) return;
    int n0  = blockIdx.x * 64;
    int off = g_off[e];
    const float* W = w13 + (size_t)e * 1024 * H;

    __shared__ uint32_t As[128][BK];
    __shared__ uint32_t Bg[64][BK];
    __shared__ uint32_t Bu[64][BK];

    int tid = threadIdx.x, lane = tid & 31, wid = tid >> 5;
    int wm = wid & 3, wn = wid >> 2;
    int grp = lane >> 2, thr = lane & 3;

    int rowA0 = tid >> 2, rowA1 = rowA0 + 64, kq = (tid & 3) * 4;
    int tA0 = (m0 + rowA0 < cnt) ? g_perm[off + m0 + rowA0] : -1;
    int tA1 = (m0 + rowA1 < cnt) ? g_perm[off + m0 + rowA1] : -1;
    int rowB = tid >> 2;

    const float4 z4 = make_float4(0.f, 0.f, 0.f, 0.f);
    float4 rA0, rA1, rG, rU;

    float cg[2][4][4], cu[2][4][4];
#pragma unroll
    for (int i = 0; i < 2; i++)
#pragma unroll
        for (int j = 0; j < 4; j++)
#pragma unroll
            for (int k = 0; k < 4; k++) { cg[i][j][k] = 0.f; cu[i][j][k] = 0.f; }

#define G1_LOAD(K0)                                                                   \
    {                                                                                 \
        rA0 = (tA0 >= 0) ? *(const float4*)&x[(size_t)tA0 * H + (K0) + kq] : z4;      \
        rA1 = (tA1 >= 0) ? *(const float4*)&x[(size_t)tA1 * H + (K0) + kq] : z4;      \
        rG  = *(const float4*)&W[(size_t)(n0 + rowB) * H + (K0) + kq];                \
        rU  = *(const float4*)&W[(size_t)(512 + n0 + rowB) * H + (K0) + kq];          \
    }

#define G1_STORE()                                                                    \
    {                                                                                 \
        As[rowA0][kq + 0] = f2tf(rA0.x); As[rowA0][kq + 1] = f2tf(rA0.y);             \
        As[rowA0][kq + 2] = f2tf(rA0.z); As[rowA0][kq + 3] = f2tf(rA0.w);             \
        As[rowA1][kq + 0] = f2tf(rA1.x); As[rowA1][kq + 1] = f2tf(rA1.y);             \
        As[rowA1][kq + 2] = f2tf(rA1.z); As[rowA1][kq + 3] = f2tf(rA1.w);             \
        Bg[rowB][kq + 0]  = f2tf(rG.x);  Bg[rowB][kq + 1]  = f2tf(rG.y);              \
        Bg[rowB][kq + 2]  = f2tf(rG.z);  Bg[rowB][kq + 3]  = f2tf(rG.w);              \
        Bu[rowB][kq + 0]  = f2tf(rU.x);  Bu[rowB][kq + 1]  = f2tf(rU.y);              \
        Bu[rowB][kq + 2]  = f2tf(rU.z);  Bu[rowB][kq + 3]  = f2tf(rU.w);              \
    }

    G1_LOAD(0);
    for (int k0 = 0; k0 < H; k0 += BK) {
        G1_STORE();
        __syncthreads();
        if (k0 + BK < H) G1_LOAD(k0 + BK);

        uint4 af[2][2];
#pragma unroll
        for (int mt = 0; mt < 2; mt++) {
            int r = wm * 32 + mt * 16 + grp;
            af[mt][0] = *(const uint4*)&As[r][thr * 4];
            af[mt][1] = *(const uint4*)&As[r + 8][thr * 4];
        }
        uint4 bgf[4], buf_[4];
#pragma unroll
        for (int nt = 0; nt < 4; nt++) {
            int c = wn * 32 + nt * 8 + grp;
            bgf[nt]  = *(const uint4*)&Bg[c][thr * 4];
            buf_[nt] = *(const uint4*)&Bu[c][thr * 4];
        }
#pragma unroll
        for (int s = 0; s < 2; s++) {
#pragma unroll
            for (int mt = 0; mt < 2; mt++) {
                const uint32_t* a0p = (const uint32_t*)&af[mt][0];
                const uint32_t* a1p = (const uint32_t*)&af[mt][1];
                uint32_t A0 = a0p[s], A1 = a1p[s], A2 = a0p[2 + s], A3 = a1p[2 + s];
#pragma unroll
                for (int nt = 0; nt < 4; nt++) {
                    const uint32_t* bp = (const uint32_t*)&bgf[nt];
                    mma8(cg[mt][nt], A0, A1, A2, A3, bp[s], bp[2 + s]);
                    const uint32_t* up = (const uint32_t*)&buf_[nt];
                    mma8(cu[mt][nt], A0, A1, A2, A3, up[s], up[2 + s]);
                }
            }
        }
        __syncthreads();
    }

    // epilogue: act = silu(g)*u
#pragma unroll
    for (int mt = 0; mt < 2; mt++) {
#pragma unroll
        for (int h2 = 0; h2 < 2; h2++) {
            int m = m0 + wm * 32 + mt * 16 + grp + h2 * 8;
            if (m < cnt) {
                size_t base = (size_t)(off + m) * FF;
#pragma unroll
                for (int nt = 0; nt < 4; nt++) {
                    int f = n0 + wn * 32 + nt * 8 + thr * 2;
                    float g0 = cg[mt][nt][h2 * 2 + 0], g1 = cg[mt][nt][h2 * 2 + 1];
                    float u0 = cu[mt][nt][h2 * 2 + 0], u1 = cu[mt][nt][h2 * 2 + 1];
                    float a0 = (g0 / (1.f + expf(-g0))) * u0;
                    float a1 = (g1 / (1.f + expf(-g1))) * u1;
                    *(float2*)&g_act[base + f] = make_float2(a0, a1);
                }
            }
        }
    }
}

// ================= GEMM2 + weighted atomic combine =================
// out[tok] += prob[r] * (act[r] . w2[e][n]),  tile M=128 x N=128. Warps 4(m) x 2(n); warp 32x64.
__global__ void __launch_bounds__(256) gemm2_kernel(const float* __restrict__ w2,
                                                    float* __restrict__ out) {
    int e   = blockIdx.z;
    int cnt = g_count[e];
    int m0  = blockIdx.y * 128;
    if (m0 >= cnt) return;
    int n0  = blockIdx.x * 128;
    int off = g_off[e];
    const float* W = w2 + (size_t)e * H * FF;

    __shared__ uint32_t As[128][BK];
    __shared__ uint32_t Bs[128][BK];

    int tid = threadIdx.x, lane = tid & 31, wid = tid >> 5;
    int wm = wid & 3, wn = wid >> 2;
    int grp = lane >> 2, thr = lane & 3;

    int rowA0 = tid >> 2, rowA1 = rowA0 + 64, kq = (tid & 3) * 4;
    bool vA0 = (m0 + rowA0 < cnt);
    bool vA1 = (m0 + rowA1 < cnt);
    size_t aBase0 = (size_t)(off + m0 + rowA0) * FF;
    size_t aBase1 = (size_t)(off + m0 + rowA1) * FF;

    const float4 z4 = make_float4(0.f, 0.f, 0.f, 0.f);
    float4 rA0, rA1, rB0, rB1;

    float acc[2][8][4];
#pragma unroll
    for (int i = 0; i < 2; i++)
#pragma unroll
        for (int j = 0; j < 8; j++)
#pragma unroll
            for (int k = 0; k < 4; k++) acc[i][j][k] = 0.f;

#define G2_LOAD(K0)                                                                   \
    {                                                                                 \
        rA0 = vA0 ? *(const float4*)&g_act[aBase0 + (K0) + kq] : z4;                  \
        rA1 = vA1 ? *(const float4*)&g_act[aBase1 + (K0) + kq] : z4;                  \
        rB0 = *(const float4*)&W[(size_t)(n0 + rowA0) * FF + (K0) + kq];              \
        rB1 = *(const float4*)&W[(size_t)(n0 + rowA1) * FF + (K0) + kq];              \
    }

#define G2_STORE()                                                                    \
    {                                                                                 \
        As[rowA0][kq + 0] = f2tf(rA0.x); As[rowA0][kq + 1] = f2tf(rA0.y);             \
        As[rowA0][kq + 2] = f2tf(rA0.z); As[rowA0][kq + 3] = f2tf(rA0.w);             \
        As[rowA1][kq + 0] = f2tf(rA1.x); As[rowA1][kq + 1] = f2tf(rA1.y);             \
        As[rowA1][kq + 2] = f2tf(rA1.z); As[rowA1][kq + 3] = f2tf(rA1.w);             \
        Bs[rowA0][kq + 0] = f2tf(rB0.x); Bs[rowA0][kq + 1] = f2tf(rB0.y);             \
        Bs[rowA0][kq + 2] = f2tf(rB0.z); Bs[rowA0][kq + 3] = f2tf(rB0.w);             \
        Bs[rowA1][kq + 0] = f2tf(rB1.x); Bs[rowA1][kq + 1] = f2tf(rB1.y);             \
        Bs[rowA1][kq + 2] = f2tf(rB1.z); Bs[rowA1][kq + 3] = f2tf(rB1.w);             \
    }

    G2_LOAD(0);
    for (int k0 = 0; k0 < FF; k0 += BK) {
        G2_STORE();
        __syncthreads();
        if (k0 + BK < FF) G2_LOAD(k0 + BK);

        uint4 af[2][2];
#pragma unroll
        for (int mt = 0; mt < 2; mt++) {
            int r = wm * 32 + mt * 16 + grp;
            af[mt][0] = *(const uint4*)&As[r][thr * 4];
            af[mt][1] = *(const uint4*)&As[r + 8][thr * 4];
        }
        uint4 bf[8];
#pragma unroll
        for (int nt = 0; nt < 8; nt++) {
            int c = wn * 64 + nt * 8 + grp;
            bf[nt] = *(const uint4*)&Bs[c][thr * 4];
        }
#pragma unroll
        for (int s = 0; s < 2; s++) {
#pragma unroll
            for (int mt = 0; mt < 2; mt++) {
                const uint32_t* a0p = (const uint32_t*)&af[mt][0];
                const uint32_t* a1p = (const uint32_t*)&af[mt][1];
                uint32_t A0 = a0p[s], A1 = a1p[s], A2 = a0p[2 + s], A3 = a1p[2 + s];
#pragma unroll
                for (int nt = 0; nt < 8; nt++) {
                    const uint32_t* bp = (const uint32_t*)&bf[nt];
                    mma8(acc[mt][nt], A0, A1, A2, A3, bp[s], bp[2 + s]);
                }
            }
        }
        __syncthreads();
    }

    // weighted combine: exactly 2 expert contributions per token -> atomicAdd
#pragma unroll
    for (int mt = 0; mt < 2; mt++) {
#pragma unroll
        for (int h2 = 0; h2 < 2; h2++) {
            int m = m0 + wm * 32 + mt * 16 + grp + h2 * 8;
            if (m < cnt) {
                int   r   = off + m;
                int   tok = g_perm[r];
                float p   = g_prob[r];
                float* o  = out + (size_t)tok * H;
#pragma unroll
                for (int nt = 0; nt < 8; nt++) {
                    int n = n0 + wn * 64 + nt * 8 + thr * 2;
                    atomicAdd(&o[n],     p * acc[mt][nt][h2 * 2 + 0]);
                    atomicAdd(&o[n + 1], p * acc[mt][nt][h2 * 2 + 1]);
                }
            }
        }
    }
}

// ---------------- launch ----------------
extern "C" void kernel_launch(void* const* d_in, const int* in_sizes, int n_in,
                              void* d_out, int out_size) {
    const float* x   = (const float*)d_in[0];
    const float* gw  = (const float*)d_in[1];
    const float* w13 = (const float*)d_in[2];
    const float* w2  = (const float*)d_in[3];
    float* out = (float*)d_out;

    zero_kernel<<<(L * H + 255) / 256, 256>>>(out);
    router_kernel<<<(L * 32 + 255) / 256, 256>>>(x, gw);
    prefix_kernel<<<1, 32>>>();
    scatter_kernel<<<(L + 255) / 256, 256>>>();
    gemm1_kernel<<<dim3(512 / 64, ROWS / 128, NE), 256>>>(x, w13);
    gemm2_kernel<<<dim3(H / 128, ROWS / 128, NE), 256>>>(w2, out);
}